// round 13
// baseline (speedup 1.0000x reference)
#include <cuda_runtime.h>
#include <math.h>

#define HD      1024
#define NROWS   50000
#define GRID    288                  // 2 CTAs/SM on >=144 SMs: co-residency safe
#define WARPS_B 8
#define TOT_WARPS (GRID * WARPS_B)   // 2304
#define NP4     (HD / 4)             // 256 float4 per vector
#define PF_ITERS 4                   // prefetch lead (iterations)

// Main 2-row rounds: as many full rounds as fit, then a 1-row balanced tail.
#define ROWS_PER_ROUND (2 * TOT_WARPS)            // 4608
#define FULL_ROUNDS    (NROWS / ROWS_PER_ROUND)   // 10
#define MAIN_ROWS      (FULL_ROUNDS * ROWS_PER_ROUND)  // 46080
#define TAIL_ROWS      (NROWS - MAIN_ROWS)        // 3920 (1-row per warp, warps 0..3919)

// Scratch (__device__ globals)
__device__ float  g_q[HD];
__device__ float  g_d2[HD];                     // W2@h_t + b2
__device__ float4 g_epartT[NP4 * GRID];         // [position][cta]
__device__ float  g_Zpart[GRID];
__device__ float  g_es[HD];
__device__ float  g_Zsum;
__device__ unsigned g_ctr[4];                   // barrier counters (monotonic)

// Grid-wide barrier, graph-replay safe: counter never resets.
__device__ __forceinline__ void gbar(int k) {
    __syncthreads();
    if (threadIdx.x == 0) {
        __threadfence();
        unsigned old = atomicAdd(&g_ctr[k], 1u);
        unsigned target = old - (old % GRID) + GRID;
        while (*(volatile unsigned*)&g_ctr[k] < target) { }
    }
    __syncthreads();
    __threadfence();
}

__device__ __forceinline__ float4 ldcs4(const float4* p) {
    float4 v;
    asm volatile("ld.global.cs.v4.f32 {%0,%1,%2,%3}, [%4];"
                 : "=f"(v.x), "=f"(v.y), "=f"(v.z), "=f"(v.w) : "l"(p));
    return v;
}
__device__ __forceinline__ void pfL2(const void* p) {
    asm volatile("prefetch.global.L2 [%0];" :: "l"(p));
}

__global__ __launch_bounds__(256, 2) void fused(
    const float* __restrict__ H,  const float* __restrict__ ht,
    const float* __restrict__ W0, const float* __restrict__ b0,
    const float* __restrict__ W1, const float* __restrict__ b1,
    const float* __restrict__ W2, const float* __restrict__ b2,
    float* __restrict__ out)
{
    __shared__ float4 sv[NP4];                 // ht -> q -> e_s (phase-local)
    __shared__ float4 se[WARPS_B][NP4];        // warp partials / reduce buf
    __shared__ float  sZ[WARPS_B];
    __shared__ float  sZtot;

    const int tid  = threadIdx.x;
    const int wid  = tid >> 5, lane = tid & 31;
    const int cta  = blockIdx.x;
    const int gw   = cta * WARPS_B + wid;      // global warp id, 0..2303

    // ---------------- Phase 1: q = W0@ht + b0 ; d2 = W2@ht + b2 --------------
    sv[tid] = ((const float4*)ht)[tid];
    __syncthreads();
    {
        // Startup prefetch: this warp's first PF_ITERS phase-2 iterations.
#pragma unroll
        for (int it = 0; it < PF_ITERS; it++) {
            long r0 = 2L * gw + it * (2L * TOT_WARPS);
            if (r0 + 1 < MAIN_ROWS) {
                pfL2(H + r0 * HD + lane * 32);
                pfL2(H + (r0 + 1) * HD + lane * 32);
            }
        }
        if (gw < 2048) {
            int j = gw & 1023;
            const float* W = (gw < 1024) ? W0 : W2;
            const float* b = (gw < 1024) ? b0 : b2;
            const float4* wr = (const float4*)(W + (size_t)j * HD);
            float4 w[8];
#pragma unroll
            for (int k = 0; k < 8; k++) w[k] = wr[lane + 32 * k];  // MLP=8
            float s = 0.f;
#pragma unroll
            for (int k = 0; k < 8; k++) {
                float4 h4 = sv[lane + 32 * k];
                s = fmaf(w[k].x, h4.x, s); s = fmaf(w[k].y, h4.y, s);
                s = fmaf(w[k].z, h4.z, s); s = fmaf(w[k].w, h4.w, s);
            }
#pragma unroll
            for (int o = 16; o; o >>= 1) s += __shfl_xor_sync(0xffffffffu, s, o);
            if (lane == 0) { if (gw < 1024) g_q[j] = s + b[j]; else g_d2[j] = s + b[j]; }
        }
    }
    gbar(0);

    // ---------------- Phase 2: pass over H, TWO rows per warp-iteration ------
    sv[tid] = __ldcg(((const float4*)g_q) + tid);
    __syncthreads();

    float4 e[8];
#pragma unroll
    for (int k = 0; k < 8; k++) e[k] = make_float4(0.f, 0.f, 0.f, 0.f);
    float Z = 0.f;

    const long pfoff = 2L * (PF_ITERS - 1) * TOT_WARPS * HD;
    for (int row = 2 * gw; row < MAIN_ROWS; row += 2 * TOT_WARPS) {
        const float* hb = H + (size_t)row * HD;
        const float4* h0 = (const float4*)hb;
        const float4* h1 = (const float4*)(hb + HD);

        // prefetch rows PF_ITERS-1 iterations ahead (tail rows prefetched too)
        {
            long prow = row + 2L * (PF_ITERS - 1) * TOT_WARPS;
            if (prow + 1 < NROWS) {
                const float* pf = hb + pfoff + lane * 32;
                pfL2(pf);
                pfL2(pf + HD);
            }
        }

        float4 r0[8], r1[8];
#pragma unroll
        for (int k = 0; k < 8; k++) r0[k] = ldcs4(h0 + lane + 32 * k);  // 16 loads
#pragma unroll
        for (int k = 0; k < 8; k++) r1[k] = ldcs4(h1 + lane + 32 * k);  // front-batched

        float s0 = 0.f, s1 = 0.f;
#pragma unroll
        for (int k = 0; k < 8; k++) {
            float4 q4 = sv[lane + 32 * k];
            s0 = fmaf(r0[k].x, q4.x, s0); s0 = fmaf(r0[k].y, q4.y, s0);
            s0 = fmaf(r0[k].z, q4.z, s0); s0 = fmaf(r0[k].w, q4.w, s0);
            s1 = fmaf(r1[k].x, q4.x, s1); s1 = fmaf(r1[k].y, q4.y, s1);
            s1 = fmaf(r1[k].z, q4.z, s1); s1 = fmaf(r1[k].w, q4.w, s1);
        }
#pragma unroll
        for (int o = 16; o; o >>= 1) {
            s0 += __shfl_xor_sync(0xffffffffu, s0, o);
            s1 += __shfl_xor_sync(0xffffffffu, s1, o);
        }

        // double exp; softmax(t)=exp(t)/sum(exp(t)) exactly, t bounded.
        float u0 = expf(expf(s0));
        float u1 = expf(expf(s1));
        Z += u0 + u1;
#pragma unroll
        for (int k = 0; k < 8; k++) {
            e[k].x = fmaf(u0, r0[k].x, fmaf(u1, r1[k].x, e[k].x));
            e[k].y = fmaf(u0, r0[k].y, fmaf(u1, r1[k].y, e[k].y));
            e[k].z = fmaf(u0, r0[k].z, fmaf(u1, r1[k].z, e[k].z));
            e[k].w = fmaf(u0, r0[k].w, fmaf(u1, r1[k].w, e[k].w));
        }
    }

    // Balanced tail: TAIL_ROWS rows, ONE row per warp (warps 0..TAIL_ROWS-1).
    if (gw < TAIL_ROWS) {
        int row = MAIN_ROWS + gw;
        const float4* h0 = (const float4*)(H + (size_t)row * HD);
        float4 r0[8];
#pragma unroll
        for (int k = 0; k < 8; k++) r0[k] = ldcs4(h0 + lane + 32 * k);
        float s0 = 0.f;
#pragma unroll
        for (int k = 0; k < 8; k++) {
            float4 q4 = sv[lane + 32 * k];
            s0 = fmaf(r0[k].x, q4.x, s0); s0 = fmaf(r0[k].y, q4.y, s0);
            s0 = fmaf(r0[k].z, q4.z, s0); s0 = fmaf(r0[k].w, q4.w, s0);
        }
#pragma unroll
        for (int o = 16; o; o >>= 1) s0 += __shfl_xor_sync(0xffffffffu, s0, o);
        float u0 = expf(expf(s0));
        Z += u0;
#pragma unroll
        for (int k = 0; k < 8; k++) {
            e[k].x = fmaf(u0, r0[k].x, e[k].x);
            e[k].y = fmaf(u0, r0[k].y, e[k].y);
            e[k].z = fmaf(u0, r0[k].z, e[k].z);
            e[k].w = fmaf(u0, r0[k].w, e[k].w);
        }
    }

    // Phase-4 CTAs: prefetch W1 slice into L2 now — overlaps other CTAs'
    // phase-2 tails and this CTA's gbar(1) wait.
    if (cta >= 128 && cta < 256) {
        int j = (cta - 128) * WARPS_B + wid;
        const float* w1r = W1 + (size_t)j * HD + lane * 32;
        pfL2(w1r); pfL2(w1r + 8 * 32);        // 2x128B per lane = full row
    }

    // CTA-level deterministic reduce of the 8 warp partials
#pragma unroll
    for (int k = 0; k < 8; k++) se[wid][lane + 32 * k] = e[k];
    if (lane == 0) sZ[wid] = Z;
    __syncthreads();
    {
        float4 acc = se[0][tid];
#pragma unroll
        for (int w = 1; w < WARPS_B; w++) {
            float4 v = se[w][tid];
            acc.x += v.x; acc.y += v.y; acc.z += v.z; acc.w += v.w;
        }
        g_epartT[tid * GRID + cta] = acc;      // position-major for phase 3
        if (tid == 0) {
            float z = 0.f;
#pragma unroll
            for (int w = 0; w < WARPS_B; w++) z += sZ[w];
            g_Zpart[cta] = z;
        }
    }
    gbar(1);

    // -------- Phase 3 (CTAs 0..127 + CTA 256) overlapped with W1 preload ----
    float4 a[8]; float bj = 0.f, dj = 0.f;     // phase-4 preloads (CTAs 128..255)
    if (cta >= 128 && cta < 256) {
        int j = (cta - 128) * WARPS_B + wid;   // 0..1023
        const float4* w1r = (const float4*)(W1 + (size_t)j * HD);
#pragma unroll
        for (int k = 0; k < 8; k++) a[k] = w1r[lane + 32 * k];  // L2 hits now
        if (lane == 0) { bj = b1[j]; dj = __ldcg(g_d2 + j); }
    } else if (cta < 128) {                    // reduce 2 positions per CTA
        int g = tid >> 7, t0 = tid & 127;      // g in {0,1}
        int p = 2 * cta + g;
        const float4* src = g_epartT + (size_t)p * GRID;
        float4 acc = __ldcg(src + t0);
        {   float4 v = __ldcg(src + t0 + 128);
            acc.x += v.x; acc.y += v.y; acc.z += v.z; acc.w += v.w; }
        if (t0 < GRID - 256) {
            float4 v = __ldcg(src + t0 + 256);
            acc.x += v.x; acc.y += v.y; acc.z += v.z; acc.w += v.w;
        }
        float4* red = &se[g * 2][0];           // two disjoint 128-entry buffers
        red[t0] = acc;
        __syncthreads();
#pragma unroll
        for (int o = 64; o; o >>= 1) {
            if (t0 < o) {
                float4 v = red[t0 + o], t = red[t0];
                t.x += v.x; t.y += v.y; t.z += v.z; t.w += v.w;
                red[t0] = t;
            }
            __syncthreads();
        }
        if (t0 == 0) ((float4*)g_es)[p] = red[0];
    } else if (cta == 256) {                   // partition function
        if (wid == 0) {
            float z = 0.f;
            for (int b = lane; b < GRID; b += 32) z += __ldcg(g_Zpart + b);
#pragma unroll
            for (int o = 16; o; o >>= 1) z += __shfl_xor_sync(0xffffffffu, z, o);
            if (lane == 0) g_Zsum = z;
        }
    }
    gbar(2);

    // ---------------- Phase 4: out = tanh(W1@e_s/Z + b1 + d2) ----------------
    if (cta >= 128 && cta < 256) {
        int j = (cta - 128) * WARPS_B + wid;
        sv[tid] = __ldcg(((const float4*)g_es) + tid);
        if (tid == 0) sZtot = __ldcg(&g_Zsum);
        __syncthreads();

        float d1 = 0.f;
#pragma unroll
        for (int k = 0; k < 8; k++) {
            float4 v = sv[lane + 32 * k];
            d1 = fmaf(a[k].x, v.x, d1); d1 = fmaf(a[k].y, v.y, d1);
            d1 = fmaf(a[k].z, v.z, d1); d1 = fmaf(a[k].w, v.w, d1);
        }
#pragma unroll
        for (int o = 16; o; o >>= 1) d1 += __shfl_xor_sync(0xffffffffu, d1, o);
        if (lane == 0)
            out[j] = tanhf(d1 / sZtot + bj + dj);
    }
}

// ---------------------------------------------------------------------------
extern "C" void kernel_launch(void* const* d_in, const int* in_sizes, int n_in,
                              void* d_out, int out_size) {
    const float* H  = (const float*)d_in[0];
    const float* ht = (const float*)d_in[1];
    const float* W0 = (const float*)d_in[2];
    const float* b0 = (const float*)d_in[3];
    const float* W1 = (const float*)d_in[4];
    const float* b1 = (const float*)d_in[5];
    const float* W2 = (const float*)d_in[6];
    const float* b2 = (const float*)d_in[7];
    float* out = (float*)d_out;

    fused<<<GRID, 256>>>(H, ht, W0, b0, W1, b1, W2, b2, out);
}

// round 15
// speedup vs baseline: 1.1121x; 1.1121x over previous
#include <cuda_runtime.h>
#include <math.h>

#define HD      1024
#define NROWS   50000
#define GRID    288                  // 2 CTAs/SM on >=144 SMs: co-residency safe
#define WARPS_B 8
#define TOT_WARPS (GRID * WARPS_B)   // 2304
#define NP4     (HD / 4)             // 256 float4 per vector
#define PF_ITERS 3                   // prefetch lead (iterations) — R12 value

// Scratch (__device__ globals)
__device__ float  g_q[HD];
__device__ float  g_d2[HD];                     // W2@h_t + b2
__device__ float4 g_epartT[NP4 * GRID];         // [position][cta]
__device__ float  g_Zpart[GRID];
__device__ float  g_es[HD];
__device__ float  g_Zsum;
__device__ unsigned g_ctr[4];                   // barrier counters (monotonic)

// Grid-wide barrier, graph-replay safe: counter never resets.
__device__ __forceinline__ void gbar(int k) {
    __syncthreads();
    if (threadIdx.x == 0) {
        __threadfence();
        unsigned old = atomicAdd(&g_ctr[k], 1u);
        unsigned target = old - (old % GRID) + GRID;
        while (*(volatile unsigned*)&g_ctr[k] < target) { }
    }
    __syncthreads();
    __threadfence();
}

__device__ __forceinline__ float4 ldcs4(const float4* p) {
    float4 v;
    asm volatile("ld.global.cs.v4.f32 {%0,%1,%2,%3}, [%4];"
                 : "=f"(v.x), "=f"(v.y), "=f"(v.z), "=f"(v.w) : "l"(p));
    return v;
}
__device__ __forceinline__ void pfL2(const void* p) {
    asm volatile("prefetch.global.L2 [%0];" :: "l"(p));
}

__global__ __launch_bounds__(256, 2) void fused(
    const float* __restrict__ H,  const float* __restrict__ ht,
    const float* __restrict__ W0, const float* __restrict__ b0,
    const float* __restrict__ W1, const float* __restrict__ b1,
    const float* __restrict__ W2, const float* __restrict__ b2,
    float* __restrict__ out)
{
    __shared__ float4 sv[NP4];                 // ht -> q -> e_s (phase-local)
    __shared__ float4 se[WARPS_B][NP4];        // warp partials / reduce buf
    __shared__ float  sZ[WARPS_B];
    __shared__ float  sZtot;

    const int tid  = threadIdx.x;
    const int wid  = tid >> 5, lane = tid & 31;
    const int cta  = blockIdx.x;
    const int gw   = cta * WARPS_B + wid;      // global warp id, 0..2303

    // ---------------- Phase 1: q = W0@ht + b0 ; d2 = W2@ht + b2 --------------
    sv[tid] = ((const float4*)ht)[tid];
    __syncthreads();
    {
        if (gw < 2048) {
            int j = gw & 1023;
            const float* W = (gw < 1024) ? W0 : W2;
            const float* b = (gw < 1024) ? b0 : b2;
            const float4* wr = (const float4*)(W + (size_t)j * HD);
            float4 w[8];
#pragma unroll
            for (int k = 0; k < 8; k++) w[k] = wr[lane + 32 * k];  // MLP=8

            // Startup prefetch: this warp's first PF_ITERS phase-2 iterations.
#pragma unroll
            for (int it = 0; it < PF_ITERS; it++) {
                long r0 = 2L * gw + it * (2L * TOT_WARPS);
                if (r0 + 1 < NROWS) {
                    pfL2(H + r0 * HD + lane * 32);
                    pfL2(H + (r0 + 1) * HD + lane * 32);
                }
            }

            float s = 0.f;
#pragma unroll
            for (int k = 0; k < 8; k++) {
                float4 h4 = sv[lane + 32 * k];
                s = fmaf(w[k].x, h4.x, s); s = fmaf(w[k].y, h4.y, s);
                s = fmaf(w[k].z, h4.z, s); s = fmaf(w[k].w, h4.w, s);
            }
#pragma unroll
            for (int o = 16; o; o >>= 1) s += __shfl_xor_sync(0xffffffffu, s, o);
            if (lane == 0) { if (gw < 1024) g_q[j] = s + b[j]; else g_d2[j] = s + b[j]; }
        } else {
#pragma unroll
            for (int it = 0; it < PF_ITERS; it++) {
                long r0 = 2L * gw + it * (2L * TOT_WARPS);
                if (r0 + 1 < NROWS) {
                    pfL2(H + r0 * HD + lane * 32);
                    pfL2(H + (r0 + 1) * HD + lane * 32);
                }
            }
        }
    }
    gbar(0);

    // ---------------- Phase 2: pass over H, TWO rows per warp-iteration ------
    // In-loop L2 prefetch keeps the DRAM->L2 pipe running 2 iterations ahead;
    // demand LDGs then mostly hit L2 (~250cyc) instead of DRAM (~600cyc).
    sv[tid] = __ldcg(((const float4*)g_q) + tid);
    __syncthreads();

    float4 e[8];
#pragma unroll
    for (int k = 0; k < 8; k++) e[k] = make_float4(0.f, 0.f, 0.f, 0.f);
    float Z = 0.f;

    const long pfoff = 2L * (PF_ITERS - 1) * TOT_WARPS * HD;   // rows at iter+PF-1
    for (int row = 2 * gw; row < NROWS; row += 2 * TOT_WARPS) {
        const float* hb = H + (size_t)row * HD;
        const float4* h0 = (const float4*)hb;
        const float4* h1 = (const float4*)(hb + HD);

        // prefetch the rows this warp will read PF_ITERS-1 iterations ahead
        {
            const float* pf = hb + pfoff + lane * 32;
            if (row + 2 * (PF_ITERS - 1) * TOT_WARPS + 1 < NROWS) {
                pfL2(pf);
                pfL2(pf + HD);
            }
        }

        float4 r0[8], r1[8];
#pragma unroll
        for (int k = 0; k < 8; k++) r0[k] = ldcs4(h0 + lane + 32 * k);  // 16 loads
#pragma unroll
        for (int k = 0; k < 8; k++) r1[k] = ldcs4(h1 + lane + 32 * k);  // front-batched

        float s0 = 0.f, s1 = 0.f;
#pragma unroll
        for (int k = 0; k < 8; k++) {
            float4 q4 = sv[lane + 32 * k];
            s0 = fmaf(r0[k].x, q4.x, s0); s0 = fmaf(r0[k].y, q4.y, s0);
            s0 = fmaf(r0[k].z, q4.z, s0); s0 = fmaf(r0[k].w, q4.w, s0);
            s1 = fmaf(r1[k].x, q4.x, s1); s1 = fmaf(r1[k].y, q4.y, s1);
            s1 = fmaf(r1[k].z, q4.z, s1); s1 = fmaf(r1[k].w, q4.w, s1);
        }
#pragma unroll
        for (int o = 16; o; o >>= 1) {
            s0 += __shfl_xor_sync(0xffffffffu, s0, o);
            s1 += __shfl_xor_sync(0xffffffffu, s1, o);
        }

        // double exp; softmax(t)=exp(t)/sum(exp(t)) exactly, t bounded.
        float u0 = expf(expf(s0));
        float u1 = expf(expf(s1));
        Z += u0 + u1;
#pragma unroll
        for (int k = 0; k < 8; k++) {
            e[k].x = fmaf(u0, r0[k].x, fmaf(u1, r1[k].x, e[k].x));
            e[k].y = fmaf(u0, r0[k].y, fmaf(u1, r1[k].y, e[k].y));
            e[k].z = fmaf(u0, r0[k].z, fmaf(u1, r1[k].z, e[k].z));
            e[k].w = fmaf(u0, r0[k].w, fmaf(u1, r1[k].w, e[k].w));
        }
    }

    // Phase-4 CTAs: prefetch W1 slice into L2 now — overlaps other CTAs'
    // phase-2 tails and this CTA's gbar(1) wait.
    if (cta >= 128 && cta < 256) {
        int j = (cta - 128) * WARPS_B + wid;
        const float* w1r = W1 + (size_t)j * HD + lane * 32;
        pfL2(w1r); pfL2(w1r + 8 * 32);        // 2x128B per lane = full row
    }

    // CTA-level deterministic reduce of the 8 warp partials
#pragma unroll
    for (int k = 0; k < 8; k++) se[wid][lane + 32 * k] = e[k];
    if (lane == 0) sZ[wid] = Z;
    __syncthreads();
    {
        float4 acc = se[0][tid];
#pragma unroll
        for (int w = 1; w < WARPS_B; w++) {
            float4 v = se[w][tid];
            acc.x += v.x; acc.y += v.y; acc.z += v.z; acc.w += v.w;
        }
        g_epartT[tid * GRID + cta] = acc;      // position-major for phase 3
        if (tid == 0) {
            float z = 0.f;
#pragma unroll
            for (int w = 0; w < WARPS_B; w++) z += sZ[w];
            g_Zpart[cta] = z;
        }
    }
    gbar(1);

    // -------- Phase 3 (CTAs 0..127 + CTA 256) overlapped with W1 preload ----
    float4 a[8]; float bj = 0.f, dj = 0.f;     // phase-4 preloads (CTAs 128..255)
    if (cta >= 128 && cta < 256) {
        int j = (cta - 128) * WARPS_B + wid;   // 0..1023
        const float4* w1r = (const float4*)(W1 + (size_t)j * HD);
#pragma unroll
        for (int k = 0; k < 8; k++) a[k] = w1r[lane + 32 * k];  // L2 hits now
        if (lane == 0) { bj = b1[j]; dj = __ldcg(g_d2 + j); }
    } else if (cta < 128) {                    // reduce 2 positions per CTA
        int g = tid >> 7, t0 = tid & 127;      // g in {0,1}
        int p = 2 * cta + g;
        const float4* src = g_epartT + (size_t)p * GRID;
        float4 acc = __ldcg(src + t0);
        {   float4 v = __ldcg(src + t0 + 128);
            acc.x += v.x; acc.y += v.y; acc.z += v.z; acc.w += v.w; }
        if (t0 < GRID - 256) {
            float4 v = __ldcg(src + t0 + 256);
            acc.x += v.x; acc.y += v.y; acc.z += v.z; acc.w += v.w;
        }
        float4* red = &se[g * 2][0];           // two disjoint 128-entry buffers
        red[t0] = acc;
        __syncthreads();
#pragma unroll
        for (int o = 64; o; o >>= 1) {
            if (t0 < o) {
                float4 v = red[t0 + o], t = red[t0];
                t.x += v.x; t.y += v.y; t.z += v.z; t.w += v.w;
                red[t0] = t;
            }
            __syncthreads();
        }
        if (t0 == 0) ((float4*)g_es)[p] = red[0];
    } else if (cta == 256) {                   // partition function
        if (wid == 0) {
            float z = 0.f;
            for (int b = lane; b < GRID; b += 32) z += __ldcg(g_Zpart + b);
#pragma unroll
            for (int o = 16; o; o >>= 1) z += __shfl_xor_sync(0xffffffffu, z, o);
            if (lane == 0) g_Zsum = z;
        }
    }
    gbar(2);

    // ---------------- Phase 4: out = tanh(W1@e_s/Z + b1 + d2) ----------------
    if (cta >= 128 && cta < 256) {
        int j = (cta - 128) * WARPS_B + wid;
        sv[tid] = __ldcg(((const float4*)g_es) + tid);
        if (tid == 0) sZtot = __ldcg(&g_Zsum);
        __syncthreads();

        float d1 = 0.f;
#pragma unroll
        for (int k = 0; k < 8; k++) {
            float4 v = sv[lane + 32 * k];
            d1 = fmaf(a[k].x, v.x, d1); d1 = fmaf(a[k].y, v.y, d1);
            d1 = fmaf(a[k].z, v.z, d1); d1 = fmaf(a[k].w, v.w, d1);
        }
#pragma unroll
        for (int o = 16; o; o >>= 1) d1 += __shfl_xor_sync(0xffffffffu, d1, o);
        if (lane == 0)
            out[j] = tanhf(d1 / sZtot + bj + dj);
    }
}

// ---------------------------------------------------------------------------
extern "C" void kernel_launch(void* const* d_in, const int* in_sizes, int n_in,
                              void* d_out, int out_size) {
    const float* H  = (const float*)d_in[0];
    const float* ht = (const float*)d_in[1];
    const float* W0 = (const float*)d_in[2];
    const float* b0 = (const float*)d_in[3];
    const float* W1 = (const float*)d_in[4];
    const float* b1 = (const float*)d_in[5];
    const float* W2 = (const float*)d_in[6];
    const float* b2 = (const float*)d_in[7];
    float* out = (float*)d_out;

    fused<<<GRID, 256>>>(H, ht, W0, b0, W1, b1, W2, b2, out);
}